// round 13
// baseline (speedup 1.0000x reference)
#include <cuda_runtime.h>
#include <math.h>

// ---------------------------------------------------------------------------
// 3-layer LSTM (H=51) + linear(2) head, B=1024, T=2048, persistent kernel.
// LAYER-PIPELINED, fat threads for register headroom: 128 CTAs x 352 threads:
//   warps 0-3 : layer-1 group (104 thr: j x b4, 4 batches), t = tk-1
//   warps 4-7 : layer-2 group (104 thr), t = tk-2
//   warps 8-9 : layer-0 group (52 thr: j, 8 batches),  t = tk
//   warp  10  : linear head, t = tk-3
// ONE __syncthreads per tick. All groups ~832 FFMA2/thread (balanced).
// fma.rn.f32x2 k-pairs, full K per thread (no shfl). Reg ceiling 186.
// ---------------------------------------------------------------------------

#define Hn    51
#define HU    52                 // padded units
#define Tn    2048
#define NBb   8
#define NCTA  128
#define NT    352
#define ABST  60                 // act batch-row stride (floats)
#define HBUF  480                // 8 * ABST
#define MROW  52                 // floats per weight row
#define MSZ   (208 * MROW)       // 10816 floats per padded matrix
#define GST   (HU * MROW)        // 2704: gate-block stride

// SMEM float offsets
#define O_WHH0 0
#define O_WIH1 10816
#define O_WHH1 21632
#define O_WIH2 32448
#define O_WHH2 43264
#define O_BIAS 54080             // [3][208]
#define O_WLIN 54704             // [2][52]
#define O_BLIN 54808             // 2 (+2 pad)
#define O_H    54812             // 6 bufs * 480 (O_H*4 % 16 == 0)
#define O_XS   57692             // [16][16]
#define SM_FLOATS 57948
#define SM_BYTES  (SM_FLOATS * 4)   // 231792 <= 232448

typedef unsigned long long ull;

__device__ __forceinline__ void f2(ull& a, ull w, ull v) {
    asm("fma.rn.f32x2 %0, %1, %2, %0;" : "+l"(a) : "l"(w), "l"(v));
}
__device__ __forceinline__ float hadd(ull v) {
    unsigned lo, hi;
    asm("mov.b64 {%0,%1}, %2;" : "=r"(lo), "=r"(hi) : "l"(v));
    return __uint_as_float(lo) + __uint_as_float(hi);
}
__device__ __forceinline__ float fsig(float x) {
    return __fdividef(1.0f, 1.0f + __expf(-x));
}
__device__ __forceinline__ float ftanh(float x) {
    return __fdividef(2.0f, 1.0f + __expf(-2.0f * x)) - 1.0f;
}

__global__ void __launch_bounds__(NT, 1) lstm_pers(
    const float* __restrict__ xin,  const float* __restrict__ tin,
    const float* __restrict__ Wih0, const float* __restrict__ Whh0,
    const float* __restrict__ bih0, const float* __restrict__ bhh0,
    const float* __restrict__ Wih1, const float* __restrict__ Whh1,
    const float* __restrict__ bih1, const float* __restrict__ bhh1,
    const float* __restrict__ Wih2, const float* __restrict__ Whh2,
    const float* __restrict__ bih2, const float* __restrict__ bhh2,
    const float* __restrict__ Wlin, const float* __restrict__ blin,
    float* __restrict__ out)
{
    extern __shared__ float sm[];
    const int tid   = threadIdx.x;
    const int bbase = blockIdx.x * NBb;

    // ---- one-time staging: padded matrices (unit 51 and col 51 = 0) ----
    {
        const float* srcs[5] = {Whh0, Wih1, Whh1, Wih2, Whh2};
        const int    dsts[5] = {O_WHH0, O_WIH1, O_WHH1, O_WIH2, O_WHH2};
        for (int w = 0; w < 5; w++) {
            const float* s = srcs[w];
            float*       d = sm + dsts[w];
            for (int i = tid; i < MSZ; i += NT) {
                int r = i / MROW, k = i - r * MROW;
                int g = r / HU,   j = r - g * HU;
                d[i] = (j < Hn && k < Hn) ? s[(g * Hn + j) * Hn + k] : 0.0f;
            }
        }
    }
    {
        const float* bi[3] = {bih0, bih1, bih2};
        const float* bh[3] = {bhh0, bhh1, bhh2};
        for (int i = tid; i < 3 * 208; i += NT) {
            int lay = i / 208, r = i - lay * 208;
            int g = r / HU, j = r - g * HU;
            sm[O_BIAS + i] = (j < Hn) ? (bi[lay][g*Hn+j] + bh[lay][g*Hn+j]) : 0.0f;
        }
    }
    for (int i = tid; i < 2 * MROW; i += NT) {
        int r = i / MROW, k = i - r * MROW;
        sm[O_WLIN + i] = (k < Hn) ? Wlin[r * Hn + k] : 0.0f;
    }
    if (tid < 2) sm[O_BLIN + tid] = blin[tid];
    for (int i = tid; i < 6 * HBUF; i += NT) sm[O_H + i] = 0.0f;

    const int wid = tid >> 5;
    int grp, lt;
    if (wid < 4)       { grp = 1; lt = tid; }
    else if (wid < 8)  { grp = 2; lt = tid - 128; }
    else if (wid < 10) { grp = 0; lt = tid - 256; }
    else               { grp = 3; lt = tid - 320; }

    // thread coordinates
    int j = 0, ob0 = 0;
    bool on = false;
    if (grp == 1 || grp == 2) { on = (lt < 104); j = lt >> 1; ob0 = (lt & 1) * 4; }
    else if (grp == 0)        { on = (lt < 52);  j = lt;      ob0 = 0; }
    if (j >= HU) { j = 0; on = false; }
    const int act0 = ob0 * ABST;

    // weight row base pointers (gate g at + g*GST)
    const float* wmA;
    const float* wmB;
    if (grp == 1)      { wmA = sm + O_WIH1 + j * MROW; wmB = sm + O_WHH1 + j * MROW; }
    else if (grp == 2) { wmA = sm + O_WIH2 + j * MROW; wmB = sm + O_WHH2 + j * MROW; }
    else               { wmA = sm + O_WHH0 + j * MROW; wmB = wmA; }

    __syncthreads();   // weights + biases staged

    float bsv[4];
    #pragma unroll
    for (int g = 0; g < 4; g++)
        bsv[g] = on ? sm[O_BIAS + grp * 208 + g * HU + j] : 0.0f;

    // L0 input weights (2 cols x 4 gates) in registers
    float wx[8];
    #pragma unroll
    for (int i = 0; i < 8; i++) wx[i] = 0.0f;
    if (grp == 0 && on && j < Hn) {
        #pragma unroll
        for (int g = 0; g < 4; g++) {
            wx[g*2+0] = Wih0[(g*Hn + j)*2 + 0];
            wx[g*2+1] = Wih0[(g*Hn + j)*2 + 1];
        }
    }

    float cs[8];
    #pragma unroll
    for (int i = 0; i < 8; i++) cs[i] = 0.0f;

    for (int tk = 0; tk <= Tn + 2; tk++) {
        __syncthreads();                      // tick barrier: prev h visible
        if ((tk & 15) == 0 && tk < Tn) {      // stage inputs for t = tk..tk+15
            if (tid < 256) {
                int tt = tid >> 4, col = tid & 15;
                float v;
                if (col < 8) v = xin[(size_t)(bbase + col) * Tn + tk + tt];
                else         v = tin[(size_t)(bbase + col - 8) * Tn + tk + tt];
                sm[O_XS + tid] = v;
            }
            __syncthreads();
        }
        const int pr = tk & 1, po = pr ^ 1;

        if (grp == 1 || grp == 2) {
            const bool run = on && ((grp == 1) ? (tk >= 1 && tk <= Tn)
                                               : (tk >= 2 && tk <= Tn + 1));
            if (run) {
                const float* xa;  const float* ha;  float* hd;
                if (grp == 1) {   // layer 1, t = tk-1: x=h0(t), h=h1(t-1)
                    xa = sm + O_H + (0*2 + po) * HBUF;
                    ha = sm + O_H + (1*2 + pr) * HBUF;
                    hd = sm + O_H + (1*2 + po) * HBUF;
                } else {          // layer 2, t = tk-2: x=h1(t), h=h2(t-1)
                    xa = sm + O_H + (1*2 + pr) * HBUF;
                    ha = sm + O_H + (2*2 + po) * HBUF;
                    hd = sm + O_H + (2*2 + pr) * HBUF;
                }
                xa += act0; ha += act0;
                ull acc[16];
                #pragma unroll
                for (int ii = 0; ii < 16; ii++) acc[ii] = 0ull;
                #pragma unroll
                for (int c = 0; c < 13; c++) {
                    ulonglong2 x0 = *(const ulonglong2*)(xa + 0*ABST + c*4);
                    ulonglong2 x1 = *(const ulonglong2*)(xa + 1*ABST + c*4);
                    ulonglong2 x2 = *(const ulonglong2*)(xa + 2*ABST + c*4);
                    ulonglong2 x3 = *(const ulonglong2*)(xa + 3*ABST + c*4);
                    ulonglong2 h0 = *(const ulonglong2*)(ha + 0*ABST + c*4);
                    ulonglong2 h1 = *(const ulonglong2*)(ha + 1*ABST + c*4);
                    ulonglong2 h2 = *(const ulonglong2*)(ha + 2*ABST + c*4);
                    ulonglong2 h3 = *(const ulonglong2*)(ha + 3*ABST + c*4);
                    #pragma unroll
                    for (int g = 0; g < 4; g++) {
                        ulonglong2 wi = *(const ulonglong2*)(wmA + g*GST + c*4);
                        ulonglong2 wh = *(const ulonglong2*)(wmB + g*GST + c*4);
                        f2(acc[g*4+0], wi.x, x0.x); f2(acc[g*4+0], wi.y, x0.y);
                        f2(acc[g*4+1], wi.x, x1.x); f2(acc[g*4+1], wi.y, x1.y);
                        f2(acc[g*4+2], wi.x, x2.x); f2(acc[g*4+2], wi.y, x2.y);
                        f2(acc[g*4+3], wi.x, x3.x); f2(acc[g*4+3], wi.y, x3.y);
                        f2(acc[g*4+0], wh.x, h0.x); f2(acc[g*4+0], wh.y, h0.y);
                        f2(acc[g*4+1], wh.x, h1.x); f2(acc[g*4+1], wh.y, h1.y);
                        f2(acc[g*4+2], wh.x, h2.x); f2(acc[g*4+2], wh.y, h2.y);
                        f2(acc[g*4+3], wh.x, h3.x); f2(acc[g*4+3], wh.y, h3.y);
                    }
                }
                float p[16];
                #pragma unroll
                for (int ii = 0; ii < 16; ii++)
                    p[ii] = hadd(acc[ii]) + bsv[ii >> 2];
                #pragma unroll
                for (int i = 0; i < 4; i++) {
                    float cn = fsig(p[4+i]) * cs[i] + fsig(p[0+i]) * ftanh(p[8+i]);
                    cs[i] = cn;
                    hd[(ob0 + i) * ABST + j] = fsig(p[12+i]) * ftanh(cn);
                }
            }
        } else if (grp == 0) {                // layer 0, t = tk
            if (on && tk < Tn) {
                const int tc = tk & 15;
                const float* ha = sm + O_H + (0*2 + po) * HBUF;   // h0(t-1)
                float*       hd = sm + O_H + (0*2 + pr) * HBUF;
                ull acc[32];
                #pragma unroll
                for (int ii = 0; ii < 32; ii++) acc[ii] = 0ull;
                #pragma unroll
                for (int c = 0; c < 13; c++) {
                    ulonglong2 av[8];
                    #pragma unroll
                    for (int i = 0; i < 8; i++)
                        av[i] = *(const ulonglong2*)(ha + i*ABST + c*4);
                    #pragma unroll
                    for (int g = 0; g < 4; g++) {
                        ulonglong2 w = *(const ulonglong2*)(wmA + g*GST + c*4);
                        #pragma unroll
                        for (int i = 0; i < 8; i++) {
                            f2(acc[g*8+i], w.x, av[i].x);
                            f2(acc[g*8+i], w.y, av[i].y);
                        }
                    }
                }
                float p[32];
                #pragma unroll
                for (int ii = 0; ii < 32; ii++)
                    p[ii] = hadd(acc[ii]) + bsv[ii >> 3];
                #pragma unroll
                for (int i = 0; i < 8; i++) {
                    float xv = sm[O_XS + tc*16 + i];
                    float tv = sm[O_XS + tc*16 + 8 + i];
                    float pi = p[0+i]  + wx[0]*xv + wx[1]*tv;
                    float pf = p[8+i]  + wx[2]*xv + wx[3]*tv;
                    float pg = p[16+i] + wx[4]*xv + wx[5]*tv;
                    float po2 = p[24+i] + wx[6]*xv + wx[7]*tv;
                    float cn = fsig(pf) * cs[i] + fsig(pi) * ftanh(pg);
                    cs[i] = cn;
                    hd[i * ABST + j] = fsig(po2) * ftanh(cn);
                }
            }
        } else {                              // head, t = tk-3
            int lane = lt & 31;
            if (lane < 16 && tk >= 3) {
                int t = tk - 3;
                int bb = lane >> 1, o = lane & 1;
                const float* hh = sm + O_H + (2*2 + (t & 1)) * HBUF + bb * ABST;
                const float* w  = sm + O_WLIN + o * MROW;
                float ssum = sm[O_BLIN + o];
                #pragma unroll
                for (int k = 0; k < Hn; k++) ssum += w[k] * hh[k];
                if (o) ssum = (ssum > 30.0f) ? ssum : log1pf(expf(ssum));
                out[(((size_t)(bbase + bb)) * Tn + (size_t)t) * 2 + o] = ssum;
            }
        }
    }
}

extern "C" void kernel_launch(void* const* d_in, const int* in_sizes, int n_in,
                              void* d_out, int out_size)
{
    (void)in_sizes; (void)n_in; (void)out_size;
    cudaFuncSetAttribute(lstm_pers, cudaFuncAttributeMaxDynamicSharedMemorySize,
                         SM_BYTES);
    lstm_pers<<<NCTA, NT, SM_BYTES>>>(
        (const float*)d_in[0],  (const float*)d_in[1],
        (const float*)d_in[2],  (const float*)d_in[3],
        (const float*)d_in[4],  (const float*)d_in[5],
        (const float*)d_in[6],  (const float*)d_in[7],
        (const float*)d_in[8],  (const float*)d_in[9],
        (const float*)d_in[10], (const float*)d_in[11],
        (const float*)d_in[12], (const float*)d_in[13],
        (const float*)d_in[14], (const float*)d_in[15],
        (float*)d_out);
}

// round 14
// speedup vs baseline: 1.0449x; 1.0449x over previous
#include <cuda_runtime.h>
#include <math.h>

// ---------------------------------------------------------------------------
// 3-layer LSTM (H=51) + linear(2) head, B=1024, T=2048, persistent kernel.
// LAYER-PIPELINED, 128 CTAs x 800 threads (25 warps):
//   warps 0-7  : layer-1 group (208 thr: j x bp, 2 batches), t = tk-1
//   warps 8-15 : layer-2 group (208 thr), t = tk-2
//   warps 16-23: layer-0 group (208 thr: j x bp, 2 batches, 1 matrix), t = tk
//   warp  24   : linear head (t = tk-3) + input staging (double-buffered XS)
// Exactly ONE __syncthreads per tick. fma.rn.f32x2 k-pairs, full K per
// thread. ABST=52 (no padding); weight & act LDS all 1-wavefront.
// ---------------------------------------------------------------------------

#define Hn    51
#define HU    52                 // padded units
#define Tn    2048
#define NBb   8
#define NCTA  128
#define NT    800
#define ABST  52                 // act batch-row stride (floats)
#define HBUF  416                // 8 * ABST
#define MROW  52                 // floats per weight row
#define MSZ   (208 * MROW)       // 10816 floats per padded matrix
#define GST   (HU * MROW)        // 2704: gate-block stride

// SMEM float offsets
#define O_WHH0 0
#define O_WIH1 10816
#define O_WHH1 21632
#define O_WIH2 32448
#define O_WHH2 43264
#define O_BIAS 54080             // [3][208]
#define O_WLIN 54704             // [2][52]
#define O_BLIN 54808             // 2 (+2 pad)
#define O_H    54812             // 6 bufs * 416  (O_H*4 % 16 == 0)
#define O_XS   57308             // [2][16][16] double-buffered input window
#define SM_FLOATS 57820
#define SM_BYTES  (SM_FLOATS * 4)   // 231280 <= 232448

typedef unsigned long long ull;

__device__ __forceinline__ void f2(ull& a, ull w, ull v) {
    asm("fma.rn.f32x2 %0, %1, %2, %0;" : "+l"(a) : "l"(w), "l"(v));
}
__device__ __forceinline__ float hadd(ull v) {
    unsigned lo, hi;
    asm("mov.b64 {%0,%1}, %2;" : "=r"(lo), "=r"(hi) : "l"(v));
    return __uint_as_float(lo) + __uint_as_float(hi);
}
__device__ __forceinline__ float fsig(float x) {
    return __fdividef(1.0f, 1.0f + __expf(-x));
}
__device__ __forceinline__ float ftanh(float x) {
    return __fdividef(2.0f, 1.0f + __expf(-2.0f * x)) - 1.0f;
}

__global__ void __launch_bounds__(NT, 1) lstm_pers(
    const float* __restrict__ xin,  const float* __restrict__ tin,
    const float* __restrict__ Wih0, const float* __restrict__ Whh0,
    const float* __restrict__ bih0, const float* __restrict__ bhh0,
    const float* __restrict__ Wih1, const float* __restrict__ Whh1,
    const float* __restrict__ bih1, const float* __restrict__ bhh1,
    const float* __restrict__ Wih2, const float* __restrict__ Whh2,
    const float* __restrict__ bih2, const float* __restrict__ bhh2,
    const float* __restrict__ Wlin, const float* __restrict__ blin,
    float* __restrict__ out)
{
    extern __shared__ float sm[];
    const int tid   = threadIdx.x;
    const int bbase = blockIdx.x * NBb;

    // ---- one-time staging: padded matrices (unit 51 and col 51 = 0) ----
    {
        const float* srcs[5] = {Whh0, Wih1, Whh1, Wih2, Whh2};
        const int    dsts[5] = {O_WHH0, O_WIH1, O_WHH1, O_WIH2, O_WHH2};
        for (int w = 0; w < 5; w++) {
            const float* s = srcs[w];
            float*       d = sm + dsts[w];
            for (int i = tid; i < MSZ; i += NT) {
                int r = i / MROW, k = i - r * MROW;
                int g = r / HU,   j = r - g * HU;
                d[i] = (j < Hn && k < Hn) ? s[(g * Hn + j) * Hn + k] : 0.0f;
            }
        }
    }
    {
        const float* bi[3] = {bih0, bih1, bih2};
        const float* bh[3] = {bhh0, bhh1, bhh2};
        for (int i = tid; i < 3 * 208; i += NT) {
            int lay = i / 208, r = i - lay * 208;
            int g = r / HU, j = r - g * HU;
            sm[O_BIAS + i] = (j < Hn) ? (bi[lay][g*Hn+j] + bh[lay][g*Hn+j]) : 0.0f;
        }
    }
    for (int i = tid; i < 2 * MROW; i += NT) {
        int r = i / MROW, k = i - r * MROW;
        sm[O_WLIN + i] = (k < Hn) ? Wlin[r * Hn + k] : 0.0f;
    }
    if (tid < 2) sm[O_BLIN + tid] = blin[tid];
    for (int i = tid; i < 6 * HBUF; i += NT) sm[O_H + i] = 0.0f;
    // initial input window (ticks 0..15) into XS buffer 0
    if (tid < 256) {
        int tt = tid >> 4, col = tid & 15;
        float v;
        if (col < 8) v = xin[(size_t)(bbase + col) * Tn + tt];
        else         v = tin[(size_t)(bbase + col - 8) * Tn + tt];
        sm[O_XS + tid] = v;
    }

    const int wid = tid >> 5;
    int grp, lt;
    if (wid < 8)       { grp = 1; lt = tid; }
    else if (wid < 16) { grp = 2; lt = tid - 256; }
    else if (wid < 24) { grp = 0; lt = tid - 512; }
    else               { grp = 3; lt = tid - 768; }

    // thread coordinates: unit j, batch pair bp -> batches ob0, ob0+1
    const bool on = (grp != 3) && (lt < 208);
    const int j   = on ? (lt >> 2) : 0;
    const int bp  = lt & 3;
    const int ob0 = bp * 2;
    const int act0 = ob0 * ABST;

    // weight row base pointers (gate g at + g*GST)
    const float* wmA;
    const float* wmB;
    if (grp == 1)      { wmA = sm + O_WIH1 + j * MROW; wmB = sm + O_WHH1 + j * MROW; }
    else if (grp == 2) { wmA = sm + O_WIH2 + j * MROW; wmB = sm + O_WHH2 + j * MROW; }
    else               { wmA = sm + O_WHH0 + j * MROW; wmB = wmA; }

    __syncthreads();   // weights + biases + initial window staged

    float bsv[4];
    #pragma unroll
    for (int g = 0; g < 4; g++)
        bsv[g] = on ? sm[O_BIAS + grp * 208 + g * HU + j] : 0.0f;

    // L0 input weights (2 cols x 4 gates) in registers
    float wx[8];
    #pragma unroll
    for (int i = 0; i < 8; i++) wx[i] = 0.0f;
    if (grp == 0 && on && j < Hn) {
        #pragma unroll
        for (int g = 0; g < 4; g++) {
            wx[g*2+0] = Wih0[(g*Hn + j)*2 + 0];
            wx[g*2+1] = Wih0[(g*Hn + j)*2 + 1];
        }
    }

    float cs0 = 0.f, cs1 = 0.f;

    for (int tk = 0; tk <= Tn + 2; tk++) {
        __syncthreads();                      // the ONLY per-tick barrier
        const int pr = tk & 1, po = pr ^ 1;

        if (grp == 1 || grp == 2) {
            const bool run = on && ((grp == 1) ? (tk >= 1 && tk <= Tn)
                                               : (tk >= 2 && tk <= Tn + 1));
            if (run) {
                const float* xa;  const float* ha;  float* hd;
                if (grp == 1) {   // layer 1, t = tk-1: x=h0(t), h=h1(t-1)
                    xa = sm + O_H + (0*2 + po) * HBUF;
                    ha = sm + O_H + (1*2 + pr) * HBUF;
                    hd = sm + O_H + (1*2 + po) * HBUF;
                } else {          // layer 2, t = tk-2: x=h1(t), h=h2(t-1)
                    xa = sm + O_H + (1*2 + pr) * HBUF;
                    ha = sm + O_H + (2*2 + po) * HBUF;
                    hd = sm + O_H + (2*2 + pr) * HBUF;
                }
                xa += act0; ha += act0;
                ull acc[8];
                #pragma unroll
                for (int ii = 0; ii < 8; ii++) acc[ii] = 0ull;
                #pragma unroll
                for (int c = 0; c < 13; c++) {
                    ulonglong2 x0 = *(const ulonglong2*)(xa + c*4);
                    ulonglong2 x1 = *(const ulonglong2*)(xa + ABST + c*4);
                    ulonglong2 h0 = *(const ulonglong2*)(ha + c*4);
                    ulonglong2 h1 = *(const ulonglong2*)(ha + ABST + c*4);
                    #pragma unroll
                    for (int g = 0; g < 4; g++) {
                        ulonglong2 wi = *(const ulonglong2*)(wmA + g*GST + c*4);
                        ulonglong2 wh = *(const ulonglong2*)(wmB + g*GST + c*4);
                        f2(acc[g*2+0], wi.x, x0.x); f2(acc[g*2+0], wi.y, x0.y);
                        f2(acc[g*2+1], wi.x, x1.x); f2(acc[g*2+1], wi.y, x1.y);
                        f2(acc[g*2+0], wh.x, h0.x); f2(acc[g*2+0], wh.y, h0.y);
                        f2(acc[g*2+1], wh.x, h1.x); f2(acc[g*2+1], wh.y, h1.y);
                    }
                }
                float p[8];
                #pragma unroll
                for (int ii = 0; ii < 8; ii++)
                    p[ii] = hadd(acc[ii]) + bsv[ii >> 1];
                float cn0 = fsig(p[2]) * cs0 + fsig(p[0]) * ftanh(p[4]);
                float cn1 = fsig(p[3]) * cs1 + fsig(p[1]) * ftanh(p[5]);
                cs0 = cn0; cs1 = cn1;
                hd[(ob0 + 0) * ABST + j] = fsig(p[6]) * ftanh(cn0);
                hd[(ob0 + 1) * ABST + j] = fsig(p[7]) * ftanh(cn1);
            }
        } else if (grp == 0) {                // layer 0, t = tk
            if (on && tk < Tn) {
                const int tc = tk & 15;
                const int xb = (tk >> 4) & 1;
                const float* ha = sm + O_H + (0*2 + po) * HBUF + act0;  // h0(t-1)
                float*       hd = sm + O_H + (0*2 + pr) * HBUF;
                ull acc[8];
                #pragma unroll
                for (int ii = 0; ii < 8; ii++) acc[ii] = 0ull;
                #pragma unroll
                for (int c = 0; c < 13; c++) {
                    ulonglong2 h0 = *(const ulonglong2*)(ha + c*4);
                    ulonglong2 h1 = *(const ulonglong2*)(ha + ABST + c*4);
                    #pragma unroll
                    for (int g = 0; g < 4; g++) {
                        ulonglong2 w = *(const ulonglong2*)(wmA + g*GST + c*4);
                        f2(acc[g*2+0], w.x, h0.x); f2(acc[g*2+0], w.y, h0.y);
                        f2(acc[g*2+1], w.x, h1.x); f2(acc[g*2+1], w.y, h1.y);
                    }
                }
                float p[8];
                #pragma unroll
                for (int ii = 0; ii < 8; ii++)
                    p[ii] = hadd(acc[ii]) + bsv[ii >> 1];
                #pragma unroll
                for (int i = 0; i < 2; i++) {
                    float xv = sm[O_XS + xb*256 + tc*16 + ob0 + i];
                    float tv = sm[O_XS + xb*256 + tc*16 + 8 + ob0 + i];
                    float pi = p[0+i] + wx[0]*xv + wx[1]*tv;
                    float pf = p[2+i] + wx[2]*xv + wx[3]*tv;
                    float pg = p[4+i] + wx[4]*xv + wx[5]*tv;
                    float pq = p[6+i] + wx[6]*xv + wx[7]*tv;
                    float cold = i ? cs1 : cs0;
                    float cn = fsig(pf) * cold + fsig(pi) * ftanh(pg);
                    if (i) cs1 = cn; else cs0 = cn;
                    hd[(ob0 + i) * ABST + j] = fsig(pq) * ftanh(cn);
                }
            }
        } else {                              // head (t = tk-3) + staging
            const int lane = lt;              // 0..31
            // stage next 16-tick input window into the other XS buffer
            if ((tk & 15) == 0) {
                const int wn = (tk >> 4) + 1;
                if (wn * 16 < Tn) {
                    const int dst = O_XS + (wn & 1) * 256;
                    #pragma unroll
                    for (int it = 0; it < 8; it++) {
                        int i = lane + it * 32;
                        int tt = i >> 4, col = i & 15;
                        float v;
                        if (col < 8) v = xin[(size_t)(bbase + col) * Tn + wn*16 + tt];
                        else         v = tin[(size_t)(bbase + col - 8) * Tn + wn*16 + tt];
                        sm[dst + i] = v;
                    }
                }
            }
            if (lane < 16 && tk >= 3) {
                int t = tk - 3;
                int bb = lane >> 1, o = lane & 1;
                const float* hh = sm + O_H + (2*2 + (t & 1)) * HBUF + bb * ABST;
                const float* w  = sm + O_WLIN + o * MROW;
                float ssum = sm[O_BLIN + o];
                #pragma unroll
                for (int k = 0; k < Hn; k++) ssum += w[k] * hh[k];
                if (o) ssum = (ssum > 30.0f) ? ssum : log1pf(expf(ssum));
                out[(((size_t)(bbase + bb)) * Tn + (size_t)t) * 2 + o] = ssum;
            }
        }
    }
}

extern "C" void kernel_launch(void* const* d_in, const int* in_sizes, int n_in,
                              void* d_out, int out_size)
{
    (void)in_sizes; (void)n_in; (void)out_size;
    cudaFuncSetAttribute(lstm_pers, cudaFuncAttributeMaxDynamicSharedMemorySize,
                         SM_BYTES);
    lstm_pers<<<NCTA, NT, SM_BYTES>>>(
        (const float*)d_in[0],  (const float*)d_in[1],
        (const float*)d_in[2],  (const float*)d_in[3],
        (const float*)d_in[4],  (const float*)d_in[5],
        (const float*)d_in[6],  (const float*)d_in[7],
        (const float*)d_in[8],  (const float*)d_in[9],
        (const float*)d_in[10], (const float*)d_in[11],
        (const float*)d_in[12], (const float*)d_in[13],
        (const float*)d_in[14], (const float*)d_in[15],
        (float*)d_out);
}

// round 15
// speedup vs baseline: 1.0545x; 1.0091x over previous
#include <cuda_runtime.h>
#include <math.h>

// ---------------------------------------------------------------------------
// 3-layer LSTM (H=51) + linear(2) head, B=1024, T=2048, persistent kernel.
// LAYER-PIPELINED + software-pipelined loads: 128 CTAs x 608 threads (19 w):
//   warps 0-6  : layer-1 (208 thr: j x bp, 2 batches), t = tk-1
//   warps 7-13 : layer-2 (208 thr), t = tk-2
//   warps 14-17: layer-0 (104 thr: j x bhalf, 4 batches), t = tk
//   warp  18   : linear head (t = tk-3) + input staging (double-buffered XS)
// ONE __syncthreads per tick. Act loads explicitly prefetched one chunk
// ahead so LDS and FMA interleave in each warp (anti phase-oscillation).
// fma.rn.f32x2 k-pairs, full K per thread. Reg ceiling 107.
// ---------------------------------------------------------------------------

#define Hn    51
#define HU    52                 // padded units
#define Tn    2048
#define NBb   8
#define NCTA  128
#define NT    608
#define ABST  52                 // act batch-row stride (floats)
#define HBUF  416                // 8 * ABST
#define MROW  52                 // floats per weight row
#define MSZ   (208 * MROW)       // 10816 floats per padded matrix
#define GST   (HU * MROW)        // 2704: gate-block stride

// SMEM float offsets
#define O_WHH0 0
#define O_WIH1 10816
#define O_WHH1 21632
#define O_WIH2 32448
#define O_WHH2 43264
#define O_BIAS 54080             // [3][208]
#define O_WLIN 54704             // [2][52]
#define O_BLIN 54808             // 2 (+2 pad)
#define O_H    54812             // 6 bufs * 416  (O_H*4 % 16 == 0)
#define O_XS   57308             // [2][16][16] double-buffered input window
#define SM_FLOATS 57820
#define SM_BYTES  (SM_FLOATS * 4)   // 231280 <= 232448

typedef unsigned long long ull;

__device__ __forceinline__ void f2(ull& a, ull w, ull v) {
    asm("fma.rn.f32x2 %0, %1, %2, %0;" : "+l"(a) : "l"(w), "l"(v));
}
__device__ __forceinline__ float hadd(ull v) {
    unsigned lo, hi;
    asm("mov.b64 {%0,%1}, %2;" : "=r"(lo), "=r"(hi) : "l"(v));
    return __uint_as_float(lo) + __uint_as_float(hi);
}
__device__ __forceinline__ float fsig(float x) {
    return __fdividef(1.0f, 1.0f + __expf(-x));
}
__device__ __forceinline__ float ftanh(float x) {
    return __fdividef(2.0f, 1.0f + __expf(-2.0f * x)) - 1.0f;
}

__global__ void __launch_bounds__(NT, 1) lstm_pers(
    const float* __restrict__ xin,  const float* __restrict__ tin,
    const float* __restrict__ Wih0, const float* __restrict__ Whh0,
    const float* __restrict__ bih0, const float* __restrict__ bhh0,
    const float* __restrict__ Wih1, const float* __restrict__ Whh1,
    const float* __restrict__ bih1, const float* __restrict__ bhh1,
    const float* __restrict__ Wih2, const float* __restrict__ Whh2,
    const float* __restrict__ bih2, const float* __restrict__ bhh2,
    const float* __restrict__ Wlin, const float* __restrict__ blin,
    float* __restrict__ out)
{
    extern __shared__ float sm[];
    const int tid   = threadIdx.x;
    const int bbase = blockIdx.x * NBb;

    // ---- one-time staging: padded matrices (unit 51 and col 51 = 0) ----
    {
        const float* srcs[5] = {Whh0, Wih1, Whh1, Wih2, Whh2};
        const int    dsts[5] = {O_WHH0, O_WIH1, O_WHH1, O_WIH2, O_WHH2};
        for (int w = 0; w < 5; w++) {
            const float* s = srcs[w];
            float*       d = sm + dsts[w];
            for (int i = tid; i < MSZ; i += NT) {
                int r = i / MROW, k = i - r * MROW;
                int g = r / HU,   j = r - g * HU;
                d[i] = (j < Hn && k < Hn) ? s[(g * Hn + j) * Hn + k] : 0.0f;
            }
        }
    }
    {
        const float* bi[3] = {bih0, bih1, bih2};
        const float* bh[3] = {bhh0, bhh1, bhh2};
        for (int i = tid; i < 3 * 208; i += NT) {
            int lay = i / 208, r = i - lay * 208;
            int g = r / HU, j = r - g * HU;
            sm[O_BIAS + i] = (j < Hn) ? (bi[lay][g*Hn+j] + bh[lay][g*Hn+j]) : 0.0f;
        }
    }
    for (int i = tid; i < 2 * MROW; i += NT) {
        int r = i / MROW, k = i - r * MROW;
        sm[O_WLIN + i] = (k < Hn) ? Wlin[r * Hn + k] : 0.0f;
    }
    if (tid < 2) sm[O_BLIN + tid] = blin[tid];
    for (int i = tid; i < 6 * HBUF; i += NT) sm[O_H + i] = 0.0f;
    // initial input window (ticks 0..15) into XS buffer 0
    if (tid < 256) {
        int tt = tid >> 4, col = tid & 15;
        float v;
        if (col < 8) v = xin[(size_t)(bbase + col) * Tn + tt];
        else         v = tin[(size_t)(bbase + col - 8) * Tn + tt];
        sm[O_XS + tid] = v;
    }

    const int wid = tid >> 5;
    int grp, lt;
    if (wid < 7)       { grp = 1; lt = tid; }
    else if (wid < 14) { grp = 2; lt = tid - 224; }
    else if (wid < 18) { grp = 0; lt = tid - 448; }
    else               { grp = 3; lt = tid - 576; }

    // thread coordinates
    int j = 0, ob0 = 0;
    bool on = false;
    if (grp == 1 || grp == 2) { on = (lt < 208); j = lt >> 2; ob0 = (lt & 3) * 2; }
    else if (grp == 0)        { on = (lt < 104); j = lt >> 1; ob0 = (lt & 1) * 4; }
    if (j >= HU) { j = 0; on = false; }
    const int act0 = ob0 * ABST;

    // weight row base pointers (gate g at + g*GST)
    const float* wmA;
    const float* wmB;
    if (grp == 1)      { wmA = sm + O_WIH1 + j * MROW; wmB = sm + O_WHH1 + j * MROW; }
    else if (grp == 2) { wmA = sm + O_WIH2 + j * MROW; wmB = sm + O_WHH2 + j * MROW; }
    else               { wmA = sm + O_WHH0 + j * MROW; wmB = wmA; }

    __syncthreads();   // weights + biases + initial window staged

    float bsv[4];
    #pragma unroll
    for (int g = 0; g < 4; g++)
        bsv[g] = on ? sm[O_BIAS + grp * 208 + g * HU + j] : 0.0f;

    // L0 input weights (2 cols x 4 gates) in registers
    float wx[8];
    #pragma unroll
    for (int i = 0; i < 8; i++) wx[i] = 0.0f;
    if (grp == 0 && on && j < Hn) {
        #pragma unroll
        for (int g = 0; g < 4; g++) {
            wx[g*2+0] = Wih0[(g*Hn + j)*2 + 0];
            wx[g*2+1] = Wih0[(g*Hn + j)*2 + 1];
        }
    }

    float cs[4];
    #pragma unroll
    for (int i = 0; i < 4; i++) cs[i] = 0.0f;

    for (int tk = 0; tk <= Tn + 2; tk++) {
        __syncthreads();                      // the ONLY per-tick barrier
        const int pr = tk & 1, po = pr ^ 1;

        if (grp == 1 || grp == 2) {
            const bool run = on && ((grp == 1) ? (tk >= 1 && tk <= Tn)
                                               : (tk >= 2 && tk <= Tn + 1));
            if (run) {
                const float* xa;  const float* ha;  float* hd;
                if (grp == 1) {   // layer 1, t = tk-1: x=h0(t), h=h1(t-1)
                    xa = sm + O_H + (0*2 + po) * HBUF;
                    ha = sm + O_H + (1*2 + pr) * HBUF;
                    hd = sm + O_H + (1*2 + po) * HBUF;
                } else {          // layer 2, t = tk-2: x=h1(t), h=h2(t-1)
                    xa = sm + O_H + (1*2 + pr) * HBUF;
                    ha = sm + O_H + (2*2 + po) * HBUF;
                    hd = sm + O_H + (2*2 + pr) * HBUF;
                }
                xa += act0; ha += act0;
                ull acc[8];
                #pragma unroll
                for (int ii = 0; ii < 8; ii++) acc[ii] = 0ull;
                // software pipeline: prefetch acts one chunk ahead
                ulonglong2 nx0 = *(const ulonglong2*)(xa);
                ulonglong2 nx1 = *(const ulonglong2*)(xa + ABST);
                ulonglong2 nh0 = *(const ulonglong2*)(ha);
                ulonglong2 nh1 = *(const ulonglong2*)(ha + ABST);
                #pragma unroll
                for (int c = 0; c < 13; c++) {
                    ulonglong2 x0 = nx0, x1 = nx1, h0 = nh0, h1 = nh1;
                    if (c < 12) {
                        nx0 = *(const ulonglong2*)(xa + (c+1)*4);
                        nx1 = *(const ulonglong2*)(xa + ABST + (c+1)*4);
                        nh0 = *(const ulonglong2*)(ha + (c+1)*4);
                        nh1 = *(const ulonglong2*)(ha + ABST + (c+1)*4);
                    }
                    #pragma unroll
                    for (int g = 0; g < 4; g++) {
                        ulonglong2 wi = *(const ulonglong2*)(wmA + g*GST + c*4);
                        ulonglong2 wh = *(const ulonglong2*)(wmB + g*GST + c*4);
                        f2(acc[g*2+0], wi.x, x0.x); f2(acc[g*2+0], wi.y, x0.y);
                        f2(acc[g*2+1], wi.x, x1.x); f2(acc[g*2+1], wi.y, x1.y);
                        f2(acc[g*2+0], wh.x, h0.x); f2(acc[g*2+0], wh.y, h0.y);
                        f2(acc[g*2+1], wh.x, h1.x); f2(acc[g*2+1], wh.y, h1.y);
                    }
                }
                float p[8];
                #pragma unroll
                for (int ii = 0; ii < 8; ii++)
                    p[ii] = hadd(acc[ii]) + bsv[ii >> 1];
                float cn0 = fsig(p[2]) * cs[0] + fsig(p[0]) * ftanh(p[4]);
                float cn1 = fsig(p[3]) * cs[1] + fsig(p[1]) * ftanh(p[5]);
                cs[0] = cn0; cs[1] = cn1;
                hd[(ob0 + 0) * ABST + j] = fsig(p[6]) * ftanh(cn0);
                hd[(ob0 + 1) * ABST + j] = fsig(p[7]) * ftanh(cn1);
            }
        } else if (grp == 0) {                // layer 0, t = tk
            if (on && tk < Tn) {
                const int tc = tk & 15;
                const int xb = (tk >> 4) & 1;
                const float* ha = sm + O_H + (0*2 + po) * HBUF + act0;  // h0(t-1)
                float*       hd = sm + O_H + (0*2 + pr) * HBUF;
                ull acc[16];
                #pragma unroll
                for (int ii = 0; ii < 16; ii++) acc[ii] = 0ull;
                ulonglong2 na0 = *(const ulonglong2*)(ha + 0*ABST);
                ulonglong2 na1 = *(const ulonglong2*)(ha + 1*ABST);
                ulonglong2 na2 = *(const ulonglong2*)(ha + 2*ABST);
                ulonglong2 na3 = *(const ulonglong2*)(ha + 3*ABST);
                #pragma unroll
                for (int c = 0; c < 13; c++) {
                    ulonglong2 a0 = na0, a1 = na1, a2 = na2, a3 = na3;
                    if (c < 12) {
                        na0 = *(const ulonglong2*)(ha + 0*ABST + (c+1)*4);
                        na1 = *(const ulonglong2*)(ha + 1*ABST + (c+1)*4);
                        na2 = *(const ulonglong2*)(ha + 2*ABST + (c+1)*4);
                        na3 = *(const ulonglong2*)(ha + 3*ABST + (c+1)*4);
                    }
                    #pragma unroll
                    for (int g = 0; g < 4; g++) {
                        ulonglong2 w = *(const ulonglong2*)(wmA + g*GST + c*4);
                        f2(acc[g*4+0], w.x, a0.x); f2(acc[g*4+0], w.y, a0.y);
                        f2(acc[g*4+1], w.x, a1.x); f2(acc[g*4+1], w.y, a1.y);
                        f2(acc[g*4+2], w.x, a2.x); f2(acc[g*4+2], w.y, a2.y);
                        f2(acc[g*4+3], w.x, a3.x); f2(acc[g*4+3], w.y, a3.y);
                    }
                }
                float p[16];
                #pragma unroll
                for (int ii = 0; ii < 16; ii++)
                    p[ii] = hadd(acc[ii]) + bsv[ii >> 2];
                #pragma unroll
                for (int i = 0; i < 4; i++) {
                    float xv = sm[O_XS + xb*256 + tc*16 + ob0 + i];
                    float tv = sm[O_XS + xb*256 + tc*16 + 8 + ob0 + i];
                    float pi = p[0+i]  + wx[0]*xv + wx[1]*tv;
                    float pf = p[4+i]  + wx[2]*xv + wx[3]*tv;
                    float pg = p[8+i]  + wx[4]*xv + wx[5]*tv;
                    float pq = p[12+i] + wx[6]*xv + wx[7]*tv;
                    float cn = fsig(pf) * cs[i] + fsig(pi) * ftanh(pg);
                    cs[i] = cn;
                    hd[(ob0 + i) * ABST + j] = fsig(pq) * ftanh(cn);
                }
            }
        } else {                              // head (t = tk-3) + staging
            const int lane = lt;              // 0..31
            if ((tk & 15) == 0) {
                const int wn = (tk >> 4) + 1;
                if (wn * 16 < Tn) {
                    const int dst = O_XS + (wn & 1) * 256;
                    #pragma unroll
                    for (int it = 0; it < 8; it++) {
                        int i = lane + it * 32;
                        int tt = i >> 4, col = i & 15;
                        float v;
                        if (col < 8) v = xin[(size_t)(bbase + col) * Tn + wn*16 + tt];
                        else         v = tin[(size_t)(bbase + col - 8) * Tn + wn*16 + tt];
                        sm[dst + i] = v;
                    }
                }
            }
            if (lane < 16 && tk >= 3) {
                int t = tk - 3;
                int bb = lane >> 1, o = lane & 1;
                const float* hh = sm + O_H + (2*2 + (t & 1)) * HBUF + bb * ABST;
                const float* w  = sm + O_WLIN + o * MROW;
                float ssum = sm[O_BLIN + o];
                #pragma unroll
                for (int k = 0; k < Hn; k++) ssum += w[k] * hh[k];
                if (o) ssum = (ssum > 30.0f) ? ssum : log1pf(expf(ssum));
                out[(((size_t)(bbase + bb)) * Tn + (size_t)t) * 2 + o] = ssum;
            }
        }
    }
}

extern "C" void kernel_launch(void* const* d_in, const int* in_sizes, int n_in,
                              void* d_out, int out_size)
{
    (void)in_sizes; (void)n_in; (void)out_size;
    cudaFuncSetAttribute(lstm_pers, cudaFuncAttributeMaxDynamicSharedMemorySize,
                         SM_BYTES);
    lstm_pers<<<NCTA, NT, SM_BYTES>>>(
        (const float*)d_in[0],  (const float*)d_in[1],
        (const float*)d_in[2],  (const float*)d_in[3],
        (const float*)d_in[4],  (const float*)d_in[5],
        (const float*)d_in[6],  (const float*)d_in[7],
        (const float*)d_in[8],  (const float*)d_in[9],
        (const float*)d_in[10], (const float*)d_in[11],
        (const float*)d_in[12], (const float*)d_in[13],
        (const float*)d_in[14], (const float*)d_in[15],
        (float*)d_out);
}

// round 16
// speedup vs baseline: 1.2286x; 1.1651x over previous
#include <cuda_runtime.h>
#include <math.h>

// ---------------------------------------------------------------------------
// 3-layer LSTM (H=51) + linear(2) head, B=1024, T=2048, persistent kernel.
// FLAG-SYNCED LAYER PIPELINE (no CTA-wide barrier in the main loop):
//   warps 0-3  : layer-1 group (104 thr: j x bh, 4 batches), own loop over s
//   warps 4-7  : layer-2 group (104 thr), own loop over r
//   warps 8-11 : layer-0 group (104 thr), own loop over t
//   warp  12   : head (outputs for q) + XS input staging; warps 13-15 idle
// Sync: SMEM progress counters + per-group named barriers (bar.sync drains
// STS => release) + __nanosleep spins. Groups drift, so LDS bursts and FMA
// tails of different groups interleave (anti phase-locking).
// fma.rn.f32x2 k-pairs, full K per thread, 16 u64 accumulators.
// ---------------------------------------------------------------------------

#define Hn    51
#define HU    52
#define Tn    2048
#define NBb   8
#define NCTA  128
#define NT    512
#define ABST  52                 // act batch-row stride
#define HBUF  416                // 8 * ABST
#define MROW  52
#define MSZ   (208 * MROW)
#define GST   (HU * MROW)

// SMEM float offsets
#define O_WHH0 0
#define O_WIH1 10816
#define O_WHH1 21632
#define O_WIH2 32448
#define O_WHH2 43264
#define O_BIAS 54080             // [3][208]
#define O_WLIN 54704             // [2][52]
#define O_BLIN 54808             // 2 (+2 pad)
#define O_H    54812             // 6 bufs * 416
#define O_XS   57308             // [2][256] double-buffered input window
#define O_CNT  57820             // 8 ints: c0,c1,c2,ch,cw,...
#define SM_FLOATS 57828
#define SM_BYTES  (SM_FLOATS * 4)   // 231312 <= 232448

typedef unsigned long long ull;

__device__ __forceinline__ void f2(ull& a, ull w, ull v) {
    asm("fma.rn.f32x2 %0, %1, %2, %0;" : "+l"(a) : "l"(w), "l"(v));
}
__device__ __forceinline__ float hadd(ull v) {
    unsigned lo, hi;
    asm("mov.b64 {%0,%1}, %2;" : "=r"(lo), "=r"(hi) : "l"(v));
    return __uint_as_float(lo) + __uint_as_float(hi);
}
__device__ __forceinline__ float fsig(float x) {
    return __fdividef(1.0f, 1.0f + __expf(-x));
}
__device__ __forceinline__ float ftanh(float x) {
    return __fdividef(2.0f, 1.0f + __expf(-2.0f * x)) - 1.0f;
}
__device__ __forceinline__ void waitge(volatile int* c, int v) {
    if (v > 0) { while (*c < v) __nanosleep(40); }
    asm volatile("" ::: "memory");
}
#define NBAR(id) asm volatile("bar.sync %0, 128;" :: "r"(id) : "memory")

__global__ void __launch_bounds__(NT, 1) lstm_pers(
    const float* __restrict__ xin,  const float* __restrict__ tin,
    const float* __restrict__ Wih0, const float* __restrict__ Whh0,
    const float* __restrict__ bih0, const float* __restrict__ bhh0,
    const float* __restrict__ Wih1, const float* __restrict__ Whh1,
    const float* __restrict__ bih1, const float* __restrict__ bhh1,
    const float* __restrict__ Wih2, const float* __restrict__ Whh2,
    const float* __restrict__ bih2, const float* __restrict__ bhh2,
    const float* __restrict__ Wlin, const float* __restrict__ blin,
    float* __restrict__ out)
{
    extern __shared__ float sm[];
    const int tid   = threadIdx.x;
    const int bbase = blockIdx.x * NBb;
    volatile int* cnt = (volatile int*)(sm + O_CNT);

    // ---- one-time staging ----
    {
        const float* srcs[5] = {Whh0, Wih1, Whh1, Wih2, Whh2};
        const int    dsts[5] = {O_WHH0, O_WIH1, O_WHH1, O_WIH2, O_WHH2};
        for (int w = 0; w < 5; w++) {
            const float* s = srcs[w];
            float*       d = sm + dsts[w];
            for (int i = tid; i < MSZ; i += NT) {
                int r = i / MROW, k = i - r * MROW;
                int g = r / HU,   j = r - g * HU;
                d[i] = (j < Hn && k < Hn) ? s[(g * Hn + j) * Hn + k] : 0.0f;
            }
        }
    }
    {
        const float* bi[3] = {bih0, bih1, bih2};
        const float* bh[3] = {bhh0, bhh1, bhh2};
        for (int i = tid; i < 3 * 208; i += NT) {
            int lay = i / 208, r = i - lay * 208;
            int g = r / HU, j = r - g * HU;
            sm[O_BIAS + i] = (j < Hn) ? (bi[lay][g*Hn+j] + bh[lay][g*Hn+j]) : 0.0f;
        }
    }
    for (int i = tid; i < 2 * MROW; i += NT) {
        int r = i / MROW, k = i - r * MROW;
        sm[O_WLIN + i] = (k < Hn) ? Wlin[r * Hn + k] : 0.0f;
    }
    if (tid < 2) sm[O_BLIN + tid] = blin[tid];
    for (int i = tid; i < 6 * HBUF; i += NT) sm[O_H + i] = 0.0f;
    if (tid < 256) {                       // window 0 into XS buf 0
        int tt = tid >> 4, col = tid & 15;
        float v;
        if (col < 8) v = xin[(size_t)(bbase + col) * Tn + tt];
        else         v = tin[(size_t)(bbase + col - 8) * Tn + tt];
        sm[O_XS + tid] = v;
    }
    if (tid < 8) ((int*)(sm + O_CNT))[tid] = (tid == 4) ? 1 : 0;  // cw=1
    __syncthreads();                       // the ONLY CTA-wide barrier

    const int wid = tid >> 5;
    int grp, lt;
    if (wid < 4)       { grp = 1; lt = tid; }
    else if (wid < 8)  { grp = 2; lt = tid - 128; }
    else if (wid < 12) { grp = 0; lt = tid - 256; }
    else if (wid == 12){ grp = 3; lt = tid - 384; }
    else               { return; }         // dummy warps exit

    const bool on = (grp != 3) && (lt < 104);
    const int j    = on ? (lt >> 1) : 0;
    const int bh   = lt & 1;
    const int ob0  = bh * 4;
    const int act0 = ob0 * ABST;

    const float* wmA;  const float* wmB;
    if (grp == 1)      { wmA = sm + O_WIH1 + j * MROW; wmB = sm + O_WHH1 + j * MROW; }
    else if (grp == 2) { wmA = sm + O_WIH2 + j * MROW; wmB = sm + O_WHH2 + j * MROW; }
    else               { wmA = sm + O_WHH0 + j * MROW; wmB = wmA; }

    float bsv[4];
    #pragma unroll
    for (int g = 0; g < 4; g++)
        bsv[g] = on ? sm[O_BIAS + grp * 208 + g * HU + j] : 0.0f;

    float wx[8];
    #pragma unroll
    for (int i = 0; i < 8; i++) wx[i] = 0.0f;
    if (grp == 0 && on && j < Hn) {
        #pragma unroll
        for (int g = 0; g < 4; g++) {
            wx[g*2+0] = Wih0[(g*Hn + j)*2 + 0];
            wx[g*2+1] = Wih0[(g*Hn + j)*2 + 1];
        }
    }

    float cs[4];
    #pragma unroll
    for (int i = 0; i < 4; i++) cs[i] = 0.0f;

    if (grp == 1 || grp == 2) {
        // ---- layer 1 / layer 2 group: own loop over timesteps ----
        const int cIn  = (grp == 1) ? 0 : 1;   // wait on producer counter
        const int cDn  = (grp == 1) ? 2 : 3;   // wait on consumer counter
        const int cMe  = (grp == 1) ? 1 : 2;
        const int barid = grp;                 // 1 or 2
        const int xbuf = (grp == 1) ? 0 : 2;   // x comes from layer l-1 bufs
        const int hbuf = (grp == 1) ? 2 : 4;   // own h bufs
        for (int s = 0; s < Tn; s++) {
            waitge(cnt + cIn, s + 1);          // x-act ready
            waitge(cnt + cDn, s - 1);          // own old buf consumed
            if (on) {
                const float* xa = sm + O_H + (xbuf + (s & 1)) * HBUF + act0;
                const float* ha = sm + O_H + (hbuf + ((s & 1) ^ 1)) * HBUF + act0;
                float*       hd = sm + O_H + (hbuf + (s & 1)) * HBUF;
                ull acc[16];
                #pragma unroll
                for (int ii = 0; ii < 16; ii++) acc[ii] = 0ull;
                #pragma unroll
                for (int c = 0; c < 13; c++) {
                    ulonglong2 x0 = *(const ulonglong2*)(xa + 0*ABST + c*4);
                    ulonglong2 x1 = *(const ulonglong2*)(xa + 1*ABST + c*4);
                    ulonglong2 x2 = *(const ulonglong2*)(xa + 2*ABST + c*4);
                    ulonglong2 x3 = *(const ulonglong2*)(xa + 3*ABST + c*4);
                    ulonglong2 h0 = *(const ulonglong2*)(ha + 0*ABST + c*4);
                    ulonglong2 h1 = *(const ulonglong2*)(ha + 1*ABST + c*4);
                    ulonglong2 h2 = *(const ulonglong2*)(ha + 2*ABST + c*4);
                    ulonglong2 h3 = *(const ulonglong2*)(ha + 3*ABST + c*4);
                    #pragma unroll
                    for (int g = 0; g < 4; g++) {
                        ulonglong2 wi = *(const ulonglong2*)(wmA + g*GST + c*4);
                        ulonglong2 wh = *(const ulonglong2*)(wmB + g*GST + c*4);
                        f2(acc[g*4+0], wi.x, x0.x); f2(acc[g*4+0], wi.y, x0.y);
                        f2(acc[g*4+1], wi.x, x1.x); f2(acc[g*4+1], wi.y, x1.y);
                        f2(acc[g*4+2], wi.x, x2.x); f2(acc[g*4+2], wi.y, x2.y);
                        f2(acc[g*4+3], wi.x, x3.x); f2(acc[g*4+3], wi.y, x3.y);
                        f2(acc[g*4+0], wh.x, h0.x); f2(acc[g*4+0], wh.y, h0.y);
                        f2(acc[g*4+1], wh.x, h1.x); f2(acc[g*4+1], wh.y, h1.y);
                        f2(acc[g*4+2], wh.x, h2.x); f2(acc[g*4+2], wh.y, h2.y);
                        f2(acc[g*4+3], wh.x, h3.x); f2(acc[g*4+3], wh.y, h3.y);
                    }
                }
                float p[16];
                #pragma unroll
                for (int ii = 0; ii < 16; ii++)
                    p[ii] = hadd(acc[ii]) + bsv[ii >> 2];
                #pragma unroll
                for (int i = 0; i < 4; i++) {
                    float cn = fsig(p[4+i]) * cs[i] + fsig(p[0+i]) * ftanh(p[8+i]);
                    cs[i] = cn;
                    hd[(ob0 + i) * ABST + j] = fsig(p[12+i]) * ftanh(cn);
                }
            }
            NBAR(barid);                       // group done; STS drained
            if (lt == 0) cnt[cMe] = s + 1;     // publish progress
        }
    } else if (grp == 0) {
        // ---- layer 0 group ----
        for (int t = 0; t < Tn; t++) {
            waitge(cnt + 4, (t >> 4) + 1);     // input window staged
            waitge(cnt + 1, t - 1);            // h0 old buf consumed by g1
            if (on) {
                const int tc = t & 15, xb = (t >> 4) & 1;
                const float* ha = sm + O_H + (0 + ((t & 1) ^ 1)) * HBUF + act0;
                float*       hd = sm + O_H + (0 + (t & 1)) * HBUF;
                ull acc[16];
                #pragma unroll
                for (int ii = 0; ii < 16; ii++) acc[ii] = 0ull;
                #pragma unroll
                for (int c = 0; c < 13; c++) {
                    ulonglong2 a0 = *(const ulonglong2*)(ha + 0*ABST + c*4);
                    ulonglong2 a1 = *(const ulonglong2*)(ha + 1*ABST + c*4);
                    ulonglong2 a2 = *(const ulonglong2*)(ha + 2*ABST + c*4);
                    ulonglong2 a3 = *(const ulonglong2*)(ha + 3*ABST + c*4);
                    #pragma unroll
                    for (int g = 0; g < 4; g++) {
                        ulonglong2 w = *(const ulonglong2*)(wmA + g*GST + c*4);
                        f2(acc[g*4+0], w.x, a0.x); f2(acc[g*4+0], w.y, a0.y);
                        f2(acc[g*4+1], w.x, a1.x); f2(acc[g*4+1], w.y, a1.y);
                        f2(acc[g*4+2], w.x, a2.x); f2(acc[g*4+2], w.y, a2.y);
                        f2(acc[g*4+3], w.x, a3.x); f2(acc[g*4+3], w.y, a3.y);
                    }
                }
                float p[16];
                #pragma unroll
                for (int ii = 0; ii < 16; ii++)
                    p[ii] = hadd(acc[ii]) + bsv[ii >> 2];
                #pragma unroll
                for (int i = 0; i < 4; i++) {
                    float xv = sm[O_XS + xb*256 + tc*16 + ob0 + i];
                    float tv = sm[O_XS + xb*256 + tc*16 + 8 + ob0 + i];
                    float pi = p[0+i]  + wx[0]*xv + wx[1]*tv;
                    float pf = p[4+i]  + wx[2]*xv + wx[3]*tv;
                    float pg = p[8+i]  + wx[4]*xv + wx[5]*tv;
                    float pq = p[12+i] + wx[6]*xv + wx[7]*tv;
                    float cn = fsig(pf) * cs[i] + fsig(pi) * ftanh(pg);
                    cs[i] = cn;
                    hd[(ob0 + i) * ABST + j] = fsig(pq) * ftanh(cn);
                }
            }
            NBAR(3);
            if (lt == 0) cnt[0] = t + 1;
        }
    } else {
        // ---- head warp: outputs + input staging ----
        const int lane = lt;
        for (int q = 0; q < Tn; q++) {
            waitge(cnt + 2, q + 1);            // h2(q) ready
            if ((q & 15) == 8) {               // stage next window
                const int wn = (q >> 4) + 1;
                if (wn * 16 < Tn) {
                    const int dst = O_XS + (wn & 1) * 256;
                    #pragma unroll
                    for (int it = 0; it < 8; it++) {
                        int i = lane + it * 32;
                        int tt = i >> 4, col = i & 15;
                        float v;
                        if (col < 8) v = xin[(size_t)(bbase + col) * Tn + wn*16 + tt];
                        else         v = tin[(size_t)(bbase + col - 8) * Tn + wn*16 + tt];
                        sm[dst + i] = v;
                    }
                    __syncwarp();
                    asm volatile("membar.cta;" ::: "memory");
                    if (lane == 0) cnt[4] = wn + 1;
                }
            }
            if (lane < 16) {
                int bb = lane >> 1, o = lane & 1;
                const float* hh = sm + O_H + (4 + (q & 1)) * HBUF + bb * ABST;
                const float* w  = sm + O_WLIN + o * MROW;
                float ssum = sm[O_BLIN + o];
                #pragma unroll
                for (int k = 0; k < Hn; k++) ssum += w[k] * hh[k];
                if (o) ssum = (ssum > 30.0f) ? ssum : log1pf(expf(ssum));
                out[(((size_t)(bbase + bb)) * Tn + (size_t)q) * 2 + o] = ssum;
            }
            __syncwarp();
            if (lane == 0) cnt[3] = q + 1;
        }
    }
}

extern "C" void kernel_launch(void* const* d_in, const int* in_sizes, int n_in,
                              void* d_out, int out_size)
{
    (void)in_sizes; (void)n_in; (void)out_size;
    cudaFuncSetAttribute(lstm_pers, cudaFuncAttributeMaxDynamicSharedMemorySize,
                         SM_BYTES);
    lstm_pers<<<NCTA, NT, SM_BYTES>>>(
        (const float*)d_in[0],  (const float*)d_in[1],
        (const float*)d_in[2],  (const float*)d_in[3],
        (const float*)d_in[4],  (const float*)d_in[5],
        (const float*)d_in[6],  (const float*)d_in[7],
        (const float*)d_in[8],  (const float*)d_in[9],
        (const float*)d_in[10], (const float*)d_in[11],
        (const float*)d_in[12], (const float*)d_in[13],
        (const float*)d_in[14], (const float*)d_in[15],
        (float*)d_out);
}